// round 16
// baseline (speedup 1.0000x reference)
#include <cuda_runtime.h>
#include <cuda_bf16.h>
#include <cstdint>

#define Bb 2
#define Nn 3136
#define Cc 256
#define Hh 56
#define Mtot (Bb * Nn)   // 6272

// ---------------- scratch (allocation-free) ----------------
__device__ float g_Q[Mtot * Cc];
__device__ float g_K[Mtot * Cc];
__device__ float g_V[Mtot * Cc];
__device__ __nv_bfloat16 g_xhi[Mtot * Cc], g_xlo[Mtot * Cc];
__device__ __nv_bfloat16 g_kvhi[Mtot * Cc], g_kvlo[Mtot * Cc];
__device__ __nv_bfloat16 g_ahi[Mtot * Cc], g_alo[Mtot * Cc];
__device__ __nv_bfloat16 g_whi[4 * Cc * Cc], g_wlo[4 * Cc * Cc];

// ---------------- portable (sm_80+) PTX helpers ----------------
__device__ __forceinline__ uint32_t smem_u32(const void* p) {
    uint32_t a;
    asm("{ .reg .u64 t; cvta.to.shared.u64 t, %1; cvt.u32.u64 %0, t; }" : "=r"(a) : "l"(p));
    return a;
}
__device__ __forceinline__ void cp_async16(uint32_t dst, const void* src) {
    asm volatile("cp.async.cg.shared.global [%0], [%1], 16;" :: "r"(dst), "l"(src) : "memory");
}
__device__ __forceinline__ void cp_commit() { asm volatile("cp.async.commit_group;" ::: "memory"); }
__device__ __forceinline__ void cp_wait0() { asm volatile("cp.async.wait_group 0;" ::: "memory"); }
__device__ __forceinline__ void ldsm4(uint32_t* r, uint32_t addr) {
    asm volatile("ldmatrix.sync.aligned.m8n8.x4.shared.b16 {%0,%1,%2,%3}, [%4];"
                 : "=r"(r[0]), "=r"(r[1]), "=r"(r[2]), "=r"(r[3]) : "r"(addr));
}
__device__ __forceinline__ void mma16816(float* d, const uint32_t* a, const uint32_t* b) {
    asm volatile(
        "mma.sync.aligned.m16n8k16.row.col.f32.bf16.bf16.f32 "
        "{%0,%1,%2,%3}, {%4,%5,%6,%7}, {%8,%9}, {%0,%1,%2,%3};"
        : "+f"(d[0]), "+f"(d[1]), "+f"(d[2]), "+f"(d[3])
        : "r"(a[0]), "r"(a[1]), "r"(a[2]), "r"(a[3]), "r"(b[0]), "r"(b[1]));
}

struct alignas(8) bf16x4 { __nv_bfloat162 a, b; };

// ---------------------------------------------------------------------------
// Fused split: all 6 fp32 tensors -> (hi, lo) bf16 pairs, one launch.
// Wq is pre-multiplied by the softmax scale (hd^-0.5) so Q comes out scaled.
// ---------------------------------------------------------------------------
__global__ __launch_bounds__(256) void split_all(
    const float4* __restrict__ x, const float4* __restrict__ xkv,
    const float4* __restrict__ wq, const float4* __restrict__ wk,
    const float4* __restrict__ wv, const float4* __restrict__ wp,
    __nv_bfloat162* __restrict__ xhi, __nv_bfloat162* __restrict__ xlo,
    __nv_bfloat162* __restrict__ kvhi, __nv_bfloat162* __restrict__ kvlo,
    __nv_bfloat162* __restrict__ whi, __nv_bfloat162* __restrict__ wlo) {
    int blk = blockIdx.x;
    const float4* src;
    __nv_bfloat162 *ho, *lo_;
    int idx;
    float mul = 1.0f;
    if (blk < 1568) {
        src = x; ho = xhi; lo_ = xlo; idx = blk;
    } else if (blk < 3136) {
        src = xkv; ho = kvhi; lo_ = kvlo; idx = blk - 1568;
    } else {
        int w = (blk - 3136) >> 6;
        idx = (blk - 3136) & 63;
        src = (w == 0) ? wq : (w == 1) ? wk : (w == 2) ? wv : wp;
        ho = whi + w * 32768;
        lo_ = wlo + w * 32768;
        if (w == 0) mul = 0.17677669529663687f;   // fold 32^-0.5 into Wq
    }
    int i = idx * 256 + threadIdx.x;
    float4 v = src[i];
    v.x *= mul; v.y *= mul; v.z *= mul; v.w *= mul;
    __nv_bfloat16 h0 = __float2bfloat16(v.x), h1 = __float2bfloat16(v.y);
    __nv_bfloat16 h2 = __float2bfloat16(v.z), h3 = __float2bfloat16(v.w);
    ho[2 * i + 0] = __nv_bfloat162(h0, h1);
    ho[2 * i + 1] = __nv_bfloat162(h2, h3);
    lo_[2 * i + 0] = __nv_bfloat162(__float2bfloat16(v.x - __bfloat162float(h0)),
                                    __float2bfloat16(v.y - __bfloat162float(h1)));
    lo_[2 * i + 1] = __nv_bfloat162(__float2bfloat16(v.z - __bfloat162float(h2)),
                                    __float2bfloat16(v.w - __bfloat162float(h3)));
}

// ---------------------------------------------------------------------------
// gemm_qkv: out[64 x 256] per CTA (FULL N) -> grid (98, 3) = 294 CTAs
// = exactly one wave at 2 CTAs/SM. A loaded ONCE per m-block (was 4x).
// 8 warps, warp grid 2m x 4n, warp tile 32x64. K-chunk 32, 2-stage.
// Smem rows padded to 40 bf16 (80B) -> conflict-free ldsm. ~100KB smem.
// ---------------------------------------------------------------------------
#define QK_A    5120            // 64 rows * 80B
#define QK_W    20480           // 256 rows * 80B
#define QK_STAGE 51200          // 2*QK_A + 2*QK_W
#define QK_SMEM (2 * QK_STAGE)  // 102400

__global__ __launch_bounds__(256, 2) void gemm_qkv(
    const __nv_bfloat16* __restrict__ xhi, const __nv_bfloat16* __restrict__ xlo,
    const __nv_bfloat16* __restrict__ kvhi, const __nv_bfloat16* __restrict__ kvlo,
    const __nv_bfloat16* __restrict__ whi, const __nv_bfloat16* __restrict__ wlo,
    float* __restrict__ Q, float* __restrict__ K, float* __restrict__ V) {
    extern __shared__ char sm[];
    uint32_t smu = smem_u32(sm);

    const int z = blockIdx.y;
    const int m0 = blockIdx.x * 64;
    const __nv_bfloat16* aHp = ((z == 0) ? xhi : kvhi) + (size_t)m0 * Cc;
    const __nv_bfloat16* aLp = ((z == 0) ? xlo : kvlo) + (size_t)m0 * Cc;
    const __nv_bfloat16* wHp = whi + (size_t)z * 65536;
    const __nv_bfloat16* wLp = wlo + (size_t)z * 65536;
    float* out = ((z == 0) ? Q : (z == 1) ? K : V) + (size_t)m0 * Cc;

    const int tid = threadIdx.x;
    const int wid = tid >> 5, lane = tid & 31;
    const int wm = (wid & 1) * 32, wn = (wid >> 1) * 64;

    // A: 2 mats x 64 rows x 4 vec16 = 512 slots (2/thread)
    const int arow = tid >> 2, aj = tid & 3;
    // W: 2 mats x 256 rows x 4 vec16 = 2048 slots (8/thread)

    auto load_chunk = [&](int s, int c) {
        int k0 = c * 32;
        uint32_t sb = smu + s * QK_STAGE;
        {
            size_t go = (size_t)arow * Cc + k0 + aj * 8;
            cp_async16(sb + arow * 80 + aj * 16, aHp + go);
            cp_async16(sb + QK_A + arow * 80 + aj * 16, aLp + go);
        }
#pragma unroll
        for (int h = 0; h < 4; h++) {
            int q = h * 256 + tid;            // 0..1023
            int row = q >> 2, j = q & 3;
            size_t go = (size_t)row * Cc + k0 + j * 8;
            cp_async16(sb + 2 * QK_A + row * 80 + j * 16, wHp + go);
            cp_async16(sb + 2 * QK_A + QK_W + row * 80 + j * 16, wLp + go);
        }
        cp_commit();
    };

    float acc[2][8][4];
#pragma unroll
    for (int a = 0; a < 2; a++)
#pragma unroll
        for (int b = 0; b < 8; b++)
#pragma unroll
            for (int c = 0; c < 4; c++) acc[a][b][c] = 0.0f;

    load_chunk(0, 0);

    const int r = lane & 15, kh = lane >> 4;

    for (int c = 0; c < 8; c++) {
        cp_wait0();
        __syncthreads();
        if (c + 1 < 8) load_chunk((c + 1) & 1, c + 1);

        uint32_t sAH = smu + (c & 1) * QK_STAGE;
        uint32_t sAL = sAH + QK_A;
        uint32_t sWH = sAH + 2 * QK_A;
        uint32_t sWL = sAH + 2 * QK_A + QK_W;

#pragma unroll
        for (int ks = 0; ks < 2; ks++) {
            int kcol = ks * 16 + kh * 8;
            uint32_t AH[2][4], AL[2][4];
#pragma unroll
            for (int mi = 0; mi < 2; mi++) {
                uint32_t off = (uint32_t)((wm + mi * 16 + r) * 40 + kcol) * 2;
                ldsm4(AH[mi], sAH + off);
                ldsm4(AL[mi], sAL + off);
            }
#pragma unroll
            for (int nj = 0; nj < 4; nj++) {
                uint32_t off = (uint32_t)((wn + nj * 16 + r) * 40 + kcol) * 2;
                uint32_t th[4], tl[4];
                ldsm4(th, sWH + off);
                ldsm4(tl, sWL + off);
                uint32_t BH0[2] = {th[0], th[2]}, BH1[2] = {th[1], th[3]};
                uint32_t BL0[2] = {tl[0], tl[2]}, BL1[2] = {tl[1], tl[3]};
#pragma unroll
                for (int mi = 0; mi < 2; mi++) {
                    mma16816(acc[mi][nj * 2 + 0], AH[mi], BH0);
                    mma16816(acc[mi][nj * 2 + 0], AH[mi], BL0);
                    mma16816(acc[mi][nj * 2 + 0], AL[mi], BH0);
                    mma16816(acc[mi][nj * 2 + 1], AH[mi], BH1);
                    mma16816(acc[mi][nj * 2 + 1], AH[mi], BL1);
                    mma16816(acc[mi][nj * 2 + 1], AL[mi], BH1);
                }
            }
        }
    }

    const int g = lane >> 2, tg = lane & 3;
#pragma unroll
    for (int mi = 0; mi < 2; mi++)
#pragma unroll
        for (int ni = 0; ni < 8; ni++) {
            int row = wm + mi * 16 + g;
            int col = wn + ni * 8 + tg * 2;
            *(float2*)(out + (size_t)row * Cc + col) =
                make_float2(acc[mi][ni][0], acc[mi][ni][1]);
            *(float2*)(out + (size_t)(row + 8) * Cc + col) =
                make_float2(acc[mi][ni][2], acc[mi][ni][3]);
        }
}

// ---------------------------------------------------------------------------
// gemm_out (R14 measured-best, unchanged): out = AH@WH^T + AH@WL^T + AL@WH^T
// 64x64 tile, K-chunk 64, 2-stage, split accumulators, 392 CTAs.
// ---------------------------------------------------------------------------
#define SM_MAT   9216          // 64 rows * 144 B
#define SM_STAGE 36864         // 4 * SM_MAT
#define SMEM_BYTES (2 * SM_STAGE + 256)   // 73984

__global__ __launch_bounds__(256, 3) void gemm_out(
    const __nv_bfloat16* __restrict__ Ahi, const __nv_bfloat16* __restrict__ Alo,
    const __nv_bfloat16* __restrict__ Whi, const __nv_bfloat16* __restrict__ Wlo,
    float* __restrict__ out, const float* __restrict__ bias) {
    extern __shared__ char sm[];
    uint32_t smu = smem_u32(sm);
    float* bsm = (float*)(sm + 2 * SM_STAGE);

    const int m0 = blockIdx.x * 64, n0 = blockIdx.y * 64;
    const int tid = threadIdx.x;
    const int wid = tid >> 5, lane = tid & 31;
    const int wm = (wid & 3) * 16, wn = (wid >> 2) * 32;

    if (tid < 64) bsm[tid] = bias[n0 + tid];

    const __nv_bfloat16* mats[4] = {Ahi + (size_t)m0 * Cc, Alo + (size_t)m0 * Cc,
                                    Whi + (size_t)n0 * Cc, Wlo + (size_t)n0 * Cc};

    const int r0 = tid >> 3, lj = tid & 7;

    auto load_chunk = [&](int s, int c) {
        int k0 = c * 64;
        uint32_t sb = smu + s * SM_STAGE;
#pragma unroll
        for (int m = 0; m < 4; m++) {
            const __nv_bfloat16* g = mats[m] + k0 + lj * 8;
            cp_async16(sb + m * SM_MAT + r0 * 144 + lj * 16, g + (size_t)r0 * Cc);
            cp_async16(sb + m * SM_MAT + (r0 + 32) * 144 + lj * 16,
                       g + (size_t)(r0 + 32) * Cc);
        }
        cp_commit();
    };

    float accA[4][4], accB[4][4];
#pragma unroll
    for (int a = 0; a < 4; a++)
#pragma unroll
        for (int b = 0; b < 4; b++) { accA[a][b] = 0.0f; accB[a][b] = 0.0f; }

    load_chunk(0, 0);

    const int r = lane & 15, kh = lane >> 4;

    for (int c = 0; c < 4; c++) {
        cp_wait0();
        __syncthreads();
        if (c + 1 < 4) load_chunk((c + 1) & 1, c + 1);

        uint32_t sAH = smu + (c & 1) * SM_STAGE;
        uint32_t sAL = sAH + SM_MAT;
        uint32_t sWH = sAH + 2 * SM_MAT;
        uint32_t sWL = sAH + 3 * SM_MAT;

#pragma unroll
        for (int ks = 0; ks < 4; ks++) {
            int kcol = ks * 16 + kh * 8;
            uint32_t AH[4], AL[4], BH[4][2], BL[4][2];
            {
                uint32_t off = (uint32_t)((wm + r) * 72 + kcol) * 2;
                ldsm4(AH, sAH + off);
                ldsm4(AL, sAL + off);
            }
#pragma unroll
            for (int nj = 0; nj < 2; nj++) {
                uint32_t off = (uint32_t)((wn + nj * 16 + r) * 72 + kcol) * 2;
                uint32_t th[4], tl[4];
                ldsm4(th, sWH + off);
                ldsm4(tl, sWL + off);
                BH[nj * 2 + 0][0] = th[0]; BH[nj * 2 + 0][1] = th[2];
                BH[nj * 2 + 1][0] = th[1]; BH[nj * 2 + 1][1] = th[3];
                BL[nj * 2 + 0][0] = tl[0]; BL[nj * 2 + 0][1] = tl[2];
                BL[nj * 2 + 1][0] = tl[1]; BL[nj * 2 + 1][1] = tl[3];
            }
#pragma unroll
            for (int ni = 0; ni < 4; ni++) mma16816(accA[ni], AH, BH[ni]);
#pragma unroll
            for (int ni = 0; ni < 4; ni++) mma16816(accB[ni], AH, BL[ni]);
#pragma unroll
            for (int ni = 0; ni < 4; ni++) mma16816(accB[ni], AL, BH[ni]);
        }
    }

    const int g = lane >> 2, tg = lane & 3;
#pragma unroll
    for (int ni = 0; ni < 4; ni++) {
        int row = m0 + wm + g;
        int coll = wn + ni * 8 + tg * 2;
        int col = n0 + coll;
        float2 v0 = make_float2(accA[ni][0] + accB[ni][0] + bsm[coll],
                                accA[ni][1] + accB[ni][1] + bsm[coll + 1]);
        float2 v1 = make_float2(accA[ni][2] + accB[ni][2] + bsm[coll],
                                accA[ni][3] + accB[ni][3] + bsm[coll + 1]);
        *(float2*)(out + (size_t)row * Cc + col) = v0;
        *(float2*)(out + (size_t)(row + 8) * Cc + col) = v1;
    }
}

// ---------------------------------------------------------------------------
// Local windowed attention (radius 3 -> 29 neighbors), SINGLE PASS.
// Block = 2x8 spatial strip (16 queries, 256 threads, 16 thr/query; thread
// owns 16 channels = half a head -> dot = partial + ONE shfl_xor(1)).
// Q is pre-scaled (folded into Wq). No max subtraction (scores O(1)).
// ---------------------------------------------------------------------------
__global__ __launch_bounds__(256) void local_attn(const float* __restrict__ Q,
                                                  const float* __restrict__ K,
                                                  const float* __restrict__ V,
                                                  __nv_bfloat16* __restrict__ Ohi,
                                                  __nv_bfloat16* __restrict__ Olo) {
    const int pid = blockIdx.x;          // 0..391
    const int b  = pid / 196;
    const int pp = pid - b * 196;        // 28 row-pairs x 7 col-strips
    const int py = (pp / 7) * 2;
    const int px = (pp % 7) * 8;

    const int qi = threadIdx.x >> 4;     // query in strip (0..15)
    const int t  = threadIdx.x & 15;     // channel group (16 ch each)
    const int qy = py + (qi >> 3);
    const int qx = px + (qi & 7);
    const int n  = qy * Hh + qx;
    const int bn = b * Nn + n;

    const size_t coff = (size_t)bn * Cc + t * 16;
    float4 q[4];
#pragma unroll
    for (int j = 0; j < 4; j++) q[j] = *(const float4*)(Q + coff + j * 4);

    const int dy[29] = {-3,-2,-2,-2,-2,-2,-1,-1,-1,-1,-1, 0, 0, 0, 0, 0, 0, 0,
                         1, 1, 1, 1, 1, 2, 2, 2, 2, 2, 3};
    const int dx[29] = { 0,-2,-1, 0, 1, 2,-2,-1, 0, 1, 2,-3,-2,-1, 0, 1, 2, 3,
                        -2,-1, 0, 1, 2,-2,-1, 0, 1, 2, 0};

    const size_t base = (size_t)b * Nn;
    float s = 0.f;
    float4 acc[4];
#pragma unroll
    for (int j = 0; j < 4; j++) acc[j] = make_float4(0.f, 0.f, 0.f, 0.f);

#pragma unroll
    for (int i = 0; i < 29; i++) {
        int ny = qy + dy[i], nx = qx + dx[i];
        bool ok = ((unsigned)ny < (unsigned)Hh) && ((unsigned)nx < (unsigned)Hh);
        int nn = ok ? ny * Hh + nx : n;
        const float* kp = K + (base + nn) * Cc + t * 16;
        const float* vp = V + (base + nn) * Cc + t * 16;
        float p = 0.f;
#pragma unroll
        for (int j = 0; j < 4; j++) {
            float4 k4 = *(const float4*)(kp + j * 4);
            p = fmaf(q[j].x, k4.x, p);
            p = fmaf(q[j].y, k4.y, p);
            p = fmaf(q[j].z, k4.z, p);
            p = fmaf(q[j].w, k4.w, p);
        }
        p += __shfl_xor_sync(0xffffffffu, p, 1);   // partner half of the head
        float e = ok ? __expf(p) : 0.f;
        s += e;
#pragma unroll
        for (int j = 0; j < 4; j++) {
            float4 v4 = *(const float4*)(vp + j * 4);
            acc[j].x = fmaf(e, v4.x, acc[j].x);
            acc[j].y = fmaf(e, v4.y, acc[j].y);
            acc[j].z = fmaf(e, v4.z, acc[j].z);
            acc[j].w = fmaf(e, v4.w, acc[j].w);
        }
    }

    float inv = __fdividef(1.0f, s);
#pragma unroll
    for (int j = 0; j < 4; j++) {
        float4 o = make_float4(acc[j].x * inv, acc[j].y * inv,
                               acc[j].z * inv, acc[j].w * inv);
        __nv_bfloat16 h0 = __float2bfloat16(o.x), h1 = __float2bfloat16(o.y);
        __nv_bfloat16 h2 = __float2bfloat16(o.z), h3 = __float2bfloat16(o.w);
        bf16x4 hv, lv;
        hv.a = __nv_bfloat162(h0, h1);
        hv.b = __nv_bfloat162(h2, h3);
        lv.a = __nv_bfloat162(__float2bfloat16(o.x - __bfloat162float(h0)),
                              __float2bfloat16(o.y - __bfloat162float(h1)));
        lv.b = __nv_bfloat162(__float2bfloat16(o.z - __bfloat162float(h2)),
                              __float2bfloat16(o.w - __bfloat162float(h3)));
        *(bf16x4*)(Ohi + coff + j * 4) = hv;
        *(bf16x4*)(Olo + coff + j * 4) = lv;
    }
}

// ---------------------------------------------------------------------------
extern "C" void kernel_launch(void* const* d_in, const int* in_sizes, int n_in,
                              void* d_out, int out_size) {
    const float* x   = (const float*)d_in[0];
    const float* xkv = (const float*)d_in[1];
    const float* Wq  = (const float*)d_in[2];
    const float* Wk  = (const float*)d_in[3];
    const float* Wv  = (const float*)d_in[4];
    const float* Wp  = (const float*)d_in[5];
    const float* bp  = (const float*)d_in[6];
    float* out = (float*)d_out;

    float *Qp, *Kp, *Vp;
    __nv_bfloat16 *xhi, *xlo, *kvhi, *kvlo, *ahi, *alo, *whi, *wlo;
    cudaGetSymbolAddress((void**)&Qp, g_Q);
    cudaGetSymbolAddress((void**)&Kp, g_K);
    cudaGetSymbolAddress((void**)&Vp, g_V);
    cudaGetSymbolAddress((void**)&xhi, g_xhi);
    cudaGetSymbolAddress((void**)&xlo, g_xlo);
    cudaGetSymbolAddress((void**)&kvhi, g_kvhi);
    cudaGetSymbolAddress((void**)&kvlo, g_kvlo);
    cudaGetSymbolAddress((void**)&ahi, g_ahi);
    cudaGetSymbolAddress((void**)&alo, g_alo);
    cudaGetSymbolAddress((void**)&whi, g_whi);
    cudaGetSymbolAddress((void**)&wlo, g_wlo);

    cudaFuncSetAttribute(gemm_qkv, cudaFuncAttributeMaxDynamicSharedMemorySize, QK_SMEM);
    cudaFuncSetAttribute(gemm_out, cudaFuncAttributeMaxDynamicSharedMemorySize, SMEM_BYTES);

    split_all<<<3392, 256>>>((const float4*)x, (const float4*)xkv,
                             (const float4*)Wq, (const float4*)Wk,
                             (const float4*)Wv, (const float4*)Wp,
                             (__nv_bfloat162*)xhi, (__nv_bfloat162*)xlo,
                             (__nv_bfloat162*)kvhi, (__nv_bfloat162*)kvlo,
                             (__nv_bfloat162*)whi, (__nv_bfloat162*)wlo);

    dim3 gqkv(Mtot / 64, 3);            // (98, 3) = 294 CTAs = 1 wave @ 2/SM
    gemm_qkv<<<gqkv, 256, QK_SMEM>>>(xhi, xlo, kvhi, kvlo, whi, wlo, Qp, Kp, Vp);

    local_attn<<<Mtot / 16, 256>>>(Qp, Kp, Vp, ahi, alo);

    dim3 gout(Mtot / 64, Cc / 64);      // (98, 4) = 392 CTAs
    gemm_out<<<gout, 256, SMEM_BYTES>>>(ahi, alo, whi + 196608, wlo + 196608, out, bp);
}

// round 17
// speedup vs baseline: 1.2790x; 1.2790x over previous
#include <cuda_runtime.h>
#include <cuda_bf16.h>
#include <cstdint>

#define Bb 2
#define Nn 3136
#define Cc 256
#define Hh 56
#define Mtot (Bb * Nn)   // 6272

// ---------------- scratch (allocation-free) ----------------
__device__ float g_Q[Mtot * Cc];
__device__ float g_K[Mtot * Cc];
__device__ float g_V[Mtot * Cc];
__device__ __nv_bfloat16 g_xhi[Mtot * Cc], g_xlo[Mtot * Cc];
__device__ __nv_bfloat16 g_kvhi[Mtot * Cc], g_kvlo[Mtot * Cc];
__device__ __nv_bfloat16 g_ahi[Mtot * Cc], g_alo[Mtot * Cc];
__device__ __nv_bfloat16 g_whi[4 * Cc * Cc], g_wlo[4 * Cc * Cc];

// ---------------- portable (sm_80+) PTX helpers ----------------
__device__ __forceinline__ uint32_t smem_u32(const void* p) {
    uint32_t a;
    asm("{ .reg .u64 t; cvta.to.shared.u64 t, %1; cvt.u32.u64 %0, t; }" : "=r"(a) : "l"(p));
    return a;
}
__device__ __forceinline__ void cp_async16(uint32_t dst, const void* src) {
    asm volatile("cp.async.cg.shared.global [%0], [%1], 16;" :: "r"(dst), "l"(src) : "memory");
}
__device__ __forceinline__ void cp_commit() { asm volatile("cp.async.commit_group;" ::: "memory"); }
__device__ __forceinline__ void cp_wait0() { asm volatile("cp.async.wait_group 0;" ::: "memory"); }
__device__ __forceinline__ void ldsm4(uint32_t* r, uint32_t addr) {
    asm volatile("ldmatrix.sync.aligned.m8n8.x4.shared.b16 {%0,%1,%2,%3}, [%4];"
                 : "=r"(r[0]), "=r"(r[1]), "=r"(r[2]), "=r"(r[3]) : "r"(addr));
}
__device__ __forceinline__ void mma16816(float* d, const uint32_t* a, const uint32_t* b) {
    asm volatile(
        "mma.sync.aligned.m16n8k16.row.col.f32.bf16.bf16.f32 "
        "{%0,%1,%2,%3}, {%4,%5,%6,%7}, {%8,%9}, {%0,%1,%2,%3};"
        : "+f"(d[0]), "+f"(d[1]), "+f"(d[2]), "+f"(d[3])
        : "r"(a[0]), "r"(a[1]), "r"(a[2]), "r"(a[3]), "r"(b[0]), "r"(b[1]));
}

struct alignas(8) bf16x4 { __nv_bfloat162 a, b; };

// ---------------------------------------------------------------------------
// Fused split: all 6 fp32 tensors -> (hi, lo) bf16 pairs, one launch.
// Wq is pre-multiplied by the softmax scale (hd^-0.5) so Q comes out scaled.
// ---------------------------------------------------------------------------
__global__ __launch_bounds__(256) void split_all(
    const float4* __restrict__ x, const float4* __restrict__ xkv,
    const float4* __restrict__ wq, const float4* __restrict__ wk,
    const float4* __restrict__ wv, const float4* __restrict__ wp,
    __nv_bfloat162* __restrict__ xhi, __nv_bfloat162* __restrict__ xlo,
    __nv_bfloat162* __restrict__ kvhi, __nv_bfloat162* __restrict__ kvlo,
    __nv_bfloat162* __restrict__ whi, __nv_bfloat162* __restrict__ wlo) {
    int blk = blockIdx.x;
    const float4* src;
    __nv_bfloat162 *ho, *lo_;
    int idx;
    float mul = 1.0f;
    if (blk < 1568) {
        src = x; ho = xhi; lo_ = xlo; idx = blk;
    } else if (blk < 3136) {
        src = xkv; ho = kvhi; lo_ = kvlo; idx = blk - 1568;
    } else {
        int w = (blk - 3136) >> 6;
        idx = (blk - 3136) & 63;
        src = (w == 0) ? wq : (w == 1) ? wk : (w == 2) ? wv : wp;
        ho = whi + w * 32768;
        lo_ = wlo + w * 32768;
        if (w == 0) mul = 0.17677669529663687f;   // fold 32^-0.5 into Wq
    }
    int i = idx * 256 + threadIdx.x;
    float4 v = src[i];
    v.x *= mul; v.y *= mul; v.z *= mul; v.w *= mul;
    __nv_bfloat16 h0 = __float2bfloat16(v.x), h1 = __float2bfloat16(v.y);
    __nv_bfloat16 h2 = __float2bfloat16(v.z), h3 = __float2bfloat16(v.w);
    ho[2 * i + 0] = __nv_bfloat162(h0, h1);
    ho[2 * i + 1] = __nv_bfloat162(h2, h3);
    lo_[2 * i + 0] = __nv_bfloat162(__float2bfloat16(v.x - __bfloat162float(h0)),
                                    __float2bfloat16(v.y - __bfloat162float(h1)));
    lo_[2 * i + 1] = __nv_bfloat162(__float2bfloat16(v.z - __bfloat162float(h2)),
                                    __float2bfloat16(v.w - __bfloat162float(h3)));
}

// ---------------------------------------------------------------------------
// HMMA GEMM body (R14 measured-best): out = AH@WH^T + AH@WL^T + AL@WH^T (+bias)
// 256 threads = 8 warps, warp grid 4m x 2n, warp tile 16x32, block 64x64.
// K-CHUNK 64: 4 mainloop iterations. 2-stage double buffer.
// Smem rows 72 bf16 (144B) -> ldsm conflict-free. 74KB smem -> 3 CTAs/SM.
// ---------------------------------------------------------------------------
#define SM_MAT   9216          // 64 rows * 144 B
#define SM_STAGE 36864         // 4 * SM_MAT
#define N_STAGE  2
#define SMEM_BYTES (N_STAGE * SM_STAGE + 256)   // 73984

__device__ __forceinline__ void gemm_body(const __nv_bfloat16* __restrict__ Ahi,
                                          const __nv_bfloat16* __restrict__ Alo,
                                          const __nv_bfloat16* __restrict__ Whi,
                                          const __nv_bfloat16* __restrict__ Wlo,
                                          float* __restrict__ out,
                                          const float* __restrict__ bias,
                                          int m0, int n0, char* sm) {
    uint32_t smu = smem_u32(sm);
    float* bsm = (float*)(sm + N_STAGE * SM_STAGE);

    const int tid = threadIdx.x;
    const int wid = tid >> 5, lane = tid & 31;
    const int wm = (wid & 3) * 16, wn = (wid >> 2) * 32;

    if (tid < 64) bsm[tid] = bias ? bias[n0 + tid] : 0.0f;

    const __nv_bfloat16* mats[4] = {Ahi + (size_t)m0 * Cc, Alo + (size_t)m0 * Cc,
                                    Whi + (size_t)n0 * Cc, Wlo + (size_t)n0 * Cc};

    const int r0 = tid >> 3, lj = tid & 7;

    auto load_chunk = [&](int s, int c) {
        int k0 = c * 64;
        uint32_t sb = smu + s * SM_STAGE;
#pragma unroll
        for (int m = 0; m < 4; m++) {
            const __nv_bfloat16* g = mats[m] + k0 + lj * 8;
            cp_async16(sb + m * SM_MAT + r0 * 144 + lj * 16,
                       g + (size_t)r0 * Cc);
            cp_async16(sb + m * SM_MAT + (r0 + 32) * 144 + lj * 16,
                       g + (size_t)(r0 + 32) * Cc);
        }
        cp_commit();
    };

    float accA[4][4], accB[4][4];
#pragma unroll
    for (int a = 0; a < 4; a++)
#pragma unroll
        for (int b = 0; b < 4; b++) { accA[a][b] = 0.0f; accB[a][b] = 0.0f; }

    load_chunk(0, 0);

    const int r = lane & 15, kh = lane >> 4;

    for (int c = 0; c < 4; c++) {
        cp_wait0();
        __syncthreads();
        if (c + 1 < 4) load_chunk((c + 1) & 1, c + 1);

        uint32_t sAH = smu + (c & 1) * SM_STAGE;
        uint32_t sAL = sAH + SM_MAT;
        uint32_t sWH = sAH + 2 * SM_MAT;
        uint32_t sWL = sAH + 3 * SM_MAT;

#pragma unroll
        for (int ks = 0; ks < 4; ks++) {
            int kcol = ks * 16 + kh * 8;
            uint32_t AH[4], AL[4], BH[4][2], BL[4][2];
            {
                uint32_t off = (uint32_t)((wm + r) * 72 + kcol) * 2;
                ldsm4(AH, sAH + off);
                ldsm4(AL, sAL + off);
            }
#pragma unroll
            for (int nj = 0; nj < 2; nj++) {
                uint32_t off = (uint32_t)((wn + nj * 16 + r) * 72 + kcol) * 2;
                uint32_t th[4], tl[4];
                ldsm4(th, sWH + off);
                ldsm4(tl, sWL + off);
                BH[nj * 2 + 0][0] = th[0]; BH[nj * 2 + 0][1] = th[2];
                BH[nj * 2 + 1][0] = th[1]; BH[nj * 2 + 1][1] = th[3];
                BL[nj * 2 + 0][0] = tl[0]; BL[nj * 2 + 0][1] = tl[2];
                BL[nj * 2 + 1][0] = tl[1]; BL[nj * 2 + 1][1] = tl[3];
            }
#pragma unroll
            for (int ni = 0; ni < 4; ni++) mma16816(accA[ni], AH, BH[ni]);
#pragma unroll
            for (int ni = 0; ni < 4; ni++) mma16816(accB[ni], AH, BL[ni]);
#pragma unroll
            for (int ni = 0; ni < 4; ni++) mma16816(accB[ni], AL, BH[ni]);
        }
    }

    const int g = lane >> 2, tg = lane & 3;
#pragma unroll
    for (int ni = 0; ni < 4; ni++) {
        int row = m0 + wm + g;
        int coll = wn + ni * 8 + tg * 2;
        int col = n0 + coll;
        float2 v0 = make_float2(accA[ni][0] + accB[ni][0] + bsm[coll],
                                accA[ni][1] + accB[ni][1] + bsm[coll + 1]);
        float2 v1 = make_float2(accA[ni][2] + accB[ni][2] + bsm[coll],
                                accA[ni][3] + accB[ni][3] + bsm[coll + 1]);
        *(float2*)(out + (size_t)row * Cc + col) = v0;
        *(float2*)(out + (size_t)(row + 8) * Cc + col) = v1;
    }
}

// Fused Q/K/V projections: grid (98, 4, 3); z selects {x@Wq, xkv@Wk, xkv@Wv}.
__global__ __launch_bounds__(256, 3) void gemm_qkv(
    const __nv_bfloat16* __restrict__ xhi, const __nv_bfloat16* __restrict__ xlo,
    const __nv_bfloat16* __restrict__ kvhi, const __nv_bfloat16* __restrict__ kvlo,
    const __nv_bfloat16* __restrict__ whi, const __nv_bfloat16* __restrict__ wlo,
    float* __restrict__ Q, float* __restrict__ K, float* __restrict__ V) {
    extern __shared__ char sm[];
    int z = blockIdx.z;
    const __nv_bfloat16* Ahi = (z == 0) ? xhi : kvhi;
    const __nv_bfloat16* Alo = (z == 0) ? xlo : kvlo;
    const __nv_bfloat16* Wh = whi + (size_t)z * 65536;
    const __nv_bfloat16* Wl = wlo + (size_t)z * 65536;
    float* out = (z == 0) ? Q : (z == 1) ? K : V;
    gemm_body(Ahi, Alo, Wh, Wl, out, nullptr, blockIdx.x * 64, blockIdx.y * 64, sm);
}

// Output projection (with bias).
__global__ __launch_bounds__(256, 3) void gemm_out(
    const __nv_bfloat16* __restrict__ Ahi, const __nv_bfloat16* __restrict__ Alo,
    const __nv_bfloat16* __restrict__ Whi, const __nv_bfloat16* __restrict__ Wlo,
    float* __restrict__ out, const float* __restrict__ bias) {
    extern __shared__ char sm[];
    gemm_body(Ahi, Alo, Whi, Wlo, out, bias, blockIdx.x * 64, blockIdx.y * 64, sm);
}

// ---------------------------------------------------------------------------
// Local windowed attention (radius 3 -> 29 neighbors), SINGLE PASS.
// ONE WARP PER QUERY: 8 queries per 256-thread block, lane owns 8 channels
// (quarter of a head) -> dot = 8-ch partial + shfl_xor(1) + shfl_xor(2).
// Doubles resident warps (42/SM vs 21) and halves per-thread registers ->
// deeper load pipelining for the latency-bound neighbor loop.
// Q is pre-scaled (folded into Wq). No max subtraction (scores O(1)).
// ---------------------------------------------------------------------------
__global__ __launch_bounds__(256) void local_attn(const float* __restrict__ Q,
                                                  const float* __restrict__ K,
                                                  const float* __restrict__ V,
                                                  __nv_bfloat16* __restrict__ Ohi,
                                                  __nv_bfloat16* __restrict__ Olo) {
    const int qi = threadIdx.x >> 5;     // query slot (0..7), one warp each
    const int lane = threadIdx.x & 31;   // channel group: 8 channels
    const int bn = blockIdx.x * 8 + qi;
    const int b  = bn / Nn;
    const int n  = bn - b * Nn;
    const int qy = n / Hh;
    const int qx = n - qy * Hh;

    const size_t coff = (size_t)bn * Cc + lane * 8;
    float4 q0 = *(const float4*)(Q + coff);
    float4 q1 = *(const float4*)(Q + coff + 4);

    const int dy[29] = {-3,-2,-2,-2,-2,-2,-1,-1,-1,-1,-1, 0, 0, 0, 0, 0, 0, 0,
                         1, 1, 1, 1, 1, 2, 2, 2, 2, 2, 3};
    const int dx[29] = { 0,-2,-1, 0, 1, 2,-2,-1, 0, 1, 2,-3,-2,-1, 0, 1, 2, 3,
                        -2,-1, 0, 1, 2,-2,-1, 0, 1, 2, 0};

    const size_t base = (size_t)b * Nn;
    float s = 0.f;
    float4 a0 = make_float4(0.f, 0.f, 0.f, 0.f);
    float4 a1 = make_float4(0.f, 0.f, 0.f, 0.f);

#pragma unroll
    for (int i = 0; i < 29; i++) {
        int ny = qy + dy[i], nx = qx + dx[i];
        bool ok = ((unsigned)ny < (unsigned)Hh) && ((unsigned)nx < (unsigned)Hh);
        int nn = ok ? ny * Hh + nx : n;
        const float* kp = K + (base + nn) * Cc + lane * 8;
        const float* vp = V + (base + nn) * Cc + lane * 8;
        float4 k0 = *(const float4*)(kp);
        float4 k1 = *(const float4*)(kp + 4);
        float p = q0.x * k0.x + q0.y * k0.y + q0.z * k0.z + q0.w * k0.w
                + q1.x * k1.x + q1.y * k1.y + q1.z * k1.z + q1.w * k1.w;
        p += __shfl_xor_sync(0xffffffffu, p, 1);
        p += __shfl_xor_sync(0xffffffffu, p, 2);   // sum over the head's 4 lanes
        float e = ok ? __expf(p) : 0.f;
        s += e;
        float4 v0 = *(const float4*)(vp);
        float4 v1 = *(const float4*)(vp + 4);
        a0.x = fmaf(e, v0.x, a0.x); a0.y = fmaf(e, v0.y, a0.y);
        a0.z = fmaf(e, v0.z, a0.z); a0.w = fmaf(e, v0.w, a0.w);
        a1.x = fmaf(e, v1.x, a1.x); a1.y = fmaf(e, v1.y, a1.y);
        a1.z = fmaf(e, v1.z, a1.z); a1.w = fmaf(e, v1.w, a1.w);
    }

    float inv = __fdividef(1.0f, s);
    float o[8] = {a0.x * inv, a0.y * inv, a0.z * inv, a0.w * inv,
                  a1.x * inv, a1.y * inv, a1.z * inv, a1.w * inv};
    __nv_bfloat16 h[8];
    uint32_t hp[4], lp[4];
#pragma unroll
    for (int j = 0; j < 8; j++) h[j] = __float2bfloat16(o[j]);
#pragma unroll
    for (int j = 0; j < 4; j++) {
        __nv_bfloat162 hv(h[2 * j], h[2 * j + 1]);
        __nv_bfloat162 lv(__float2bfloat16(o[2 * j] - __bfloat162float(h[2 * j])),
                          __float2bfloat16(o[2 * j + 1] - __bfloat162float(h[2 * j + 1])));
        hp[j] = *(uint32_t*)&hv;
        lp[j] = *(uint32_t*)&lv;
    }
    *(uint4*)(Ohi + coff) = make_uint4(hp[0], hp[1], hp[2], hp[3]);
    *(uint4*)(Olo + coff) = make_uint4(lp[0], lp[1], lp[2], lp[3]);
}

// ---------------------------------------------------------------------------
extern "C" void kernel_launch(void* const* d_in, const int* in_sizes, int n_in,
                              void* d_out, int out_size) {
    const float* x   = (const float*)d_in[0];
    const float* xkv = (const float*)d_in[1];
    const float* Wq  = (const float*)d_in[2];
    const float* Wk  = (const float*)d_in[3];
    const float* Wv  = (const float*)d_in[4];
    const float* Wp  = (const float*)d_in[5];
    const float* bp  = (const float*)d_in[6];
    float* out = (float*)d_out;

    float *Qp, *Kp, *Vp;
    __nv_bfloat16 *xhi, *xlo, *kvhi, *kvlo, *ahi, *alo, *whi, *wlo;
    cudaGetSymbolAddress((void**)&Qp, g_Q);
    cudaGetSymbolAddress((void**)&Kp, g_K);
    cudaGetSymbolAddress((void**)&Vp, g_V);
    cudaGetSymbolAddress((void**)&xhi, g_xhi);
    cudaGetSymbolAddress((void**)&xlo, g_xlo);
    cudaGetSymbolAddress((void**)&kvhi, g_kvhi);
    cudaGetSymbolAddress((void**)&kvlo, g_kvlo);
    cudaGetSymbolAddress((void**)&ahi, g_ahi);
    cudaGetSymbolAddress((void**)&alo, g_alo);
    cudaGetSymbolAddress((void**)&whi, g_whi);
    cudaGetSymbolAddress((void**)&wlo, g_wlo);

    cudaFuncSetAttribute(gemm_qkv, cudaFuncAttributeMaxDynamicSharedMemorySize, SMEM_BYTES);
    cudaFuncSetAttribute(gemm_out, cudaFuncAttributeMaxDynamicSharedMemorySize, SMEM_BYTES);

    split_all<<<3392, 256>>>((const float4*)x, (const float4*)xkv,
                             (const float4*)Wq, (const float4*)Wk,
                             (const float4*)Wv, (const float4*)Wp,
                             (__nv_bfloat162*)xhi, (__nv_bfloat162*)xlo,
                             (__nv_bfloat162*)kvhi, (__nv_bfloat162*)kvlo,
                             (__nv_bfloat162*)whi, (__nv_bfloat162*)wlo);

    dim3 gqkv(Mtot / 64, Cc / 64, 3);   // (98, 4, 3) = 1176 CTAs
    gemm_qkv<<<gqkv, 256, SMEM_BYTES>>>(xhi, xlo, kvhi, kvlo, whi, wlo, Qp, Kp, Vp);

    local_attn<<<Mtot / 8, 256>>>(Qp, Kp, Vp, ahi, alo);

    dim3 gout(Mtot / 64, Cc / 64);      // (98, 4) = 392 CTAs
    gemm_out<<<gout, 256, SMEM_BYTES>>>(ahi, alo, whi + 196608, wlo + 196608, out, bp);
}